// round 2
// baseline (speedup 1.0000x reference)
#include <cuda_runtime.h>
#include <cuda_bf16.h>
#include <math.h>

// ---------------------------------------------------------------------------
// Problem constants
// ---------------------------------------------------------------------------
#define NB 8
#define NPTS 2048
#define BNTOT (NB*NPTS)          // 16384
#define KNN 20
#define MEDGE (BNTOT*KNN)        // 327680
#define NEG_SLOPE 0.2f
#define BN_EPS 1e-5f

// ---------------------------------------------------------------------------
// Scratch (device globals -- no allocation allowed)
// ---------------------------------------------------------------------------
__device__ float g_f0  [BNTOT*3];
__device__ float g_x1  [BNTOT*64];
__device__ float g_x2  [BNTOT*64];
__device__ float g_x3  [BNTOT*128];
__device__ float g_x4  [BNTOT*256];
__device__ float g_pd  [(size_t)NB*NPTS*NPTS];       // 134 MB
__device__ int   g_idx [MEDGE];
__device__ float g_wa  [256*128];
__device__ float g_wd  [256*128];
__device__ float g_T   [BNTOT*256];
__device__ float g_H   [(size_t)MEDGE*256];          // 335 MB
__device__ float g_hmax[BNTOT*256];
__device__ float g_hmin[BNTOT*256];
__device__ float g_P   [BNTOT*256];
__device__ float g_cat [BNTOT*768];
__device__ float g_gmax[NB*256];
__device__ double g_sum [256];
__device__ double g_sum2[256];
__device__ float g_scale[256];
__device__ float g_shift[256];

// ---------------------------------------------------------------------------
// Small elementwise kernels
// ---------------------------------------------------------------------------
__global__ void transpose_in_kernel(const float* __restrict__ x, float* __restrict__ f) {
    int i = blockIdx.x*256 + threadIdx.x;                 // B*3*N = 49152
    if (i >= NB*3*NPTS) return;
    int b = i / (3*NPTS);
    int rem = i - b*3*NPTS;
    int c = rem / NPTS;
    int n = rem - c*NPTS;
    f[(b*NPTS + n)*3 + c] = x[i];
}

__global__ void prep_w_kernel(const float* __restrict__ W, int O, int C,
                              float* __restrict__ wa, float* __restrict__ wd) {
    int i = blockIdx.x*256 + threadIdx.x;
    if (i >= O*C) return;
    int o = i / C, c = i - o*C;
    float a = W[o*2*C + c];
    wa[i] = a;
    wd[i] = W[o*2*C + C + c] - a;
}

__global__ void zero_stats_kernel(double* s, double* s2) {
    int t = threadIdx.x;
    if (t < 256) { s[t] = 0.0; s2[t] = 0.0; }
}

// ---------------------------------------------------------------------------
// Direct squared-distance kernel: pd[b,i,j] = -sum_c (x_i[c]-x_j[c])^2
// Cancellation-free: for near pairs (the only ones that matter for top-20),
// abs error ~ eps * d^2 instead of ~ eps * C. Ordering ~= true ordering.
// Tiling: 128x64 tile, 16 k-slice, 256 threads, 8x4 per thread.
// ---------------------------------------------------------------------------
__global__ __launch_bounds__(256)
void dist_kernel(const float* __restrict__ feat, float* __restrict__ pd, int C) {
    __shared__ float As[16][129];
    __shared__ float Bs[16][65];
    int b  = blockIdx.z;
    const float* F = feat + (size_t)b*NPTS*C;
    int tid = threadIdx.x;
    int tx = tid & 15;         // col group
    int ty = tid >> 4;         // row group
    int m0 = blockIdx.x * 128;
    int n0 = blockIdx.y * 64;

    float acc[8][4];
#pragma unroll
    for (int i = 0; i < 8; i++)
#pragma unroll
        for (int j = 0; j < 4; j++) acc[i][j] = 0.f;

    for (int k0 = 0; k0 < C; k0 += 16) {
#pragma unroll
        for (int i = 0; i < 8; i++) {
            int e = tid + i*256;
            int c = e & 15, r = e >> 4;
            float v = 0.f;
            if (k0 + c < C) v = F[(size_t)(m0 + r)*C + k0 + c];
            As[c][r] = v;
        }
#pragma unroll
        for (int i = 0; i < 4; i++) {
            int e = tid + i*256;
            int c = e & 15, r = e >> 4;
            float v = 0.f;
            if (k0 + c < C) v = F[(size_t)(n0 + r)*C + k0 + c];
            Bs[c][r] = v;
        }
        __syncthreads();
#pragma unroll
        for (int k = 0; k < 16; k++) {
            float af[8], bf[4];
#pragma unroll
            for (int i = 0; i < 8; i++) af[i] = As[k][ty*8 + i];
#pragma unroll
            for (int j = 0; j < 4; j++) bf[j] = Bs[k][tx*4 + j];
#pragma unroll
            for (int i = 0; i < 8; i++)
#pragma unroll
                for (int j = 0; j < 4; j++) {
                    float d = af[i] - bf[j];
                    acc[i][j] = fmaf(d, d, acc[i][j]);
                }
        }
        __syncthreads();
    }

    float* pdb = pd + (size_t)b*NPTS*NPTS;
#pragma unroll
    for (int i = 0; i < 8; i++) {
        int m = m0 + ty*8 + i;
#pragma unroll
        for (int j = 0; j < 4; j++) {
            int n = n0 + tx*4 + j;
            pdb[(size_t)m*NPTS + n] = -acc[i][j];
        }
    }
}

// ---------------------------------------------------------------------------
// Top-K (K=20) per row, iterative argmax (ties -> lower index, matches lax.top_k set)
// ---------------------------------------------------------------------------
__global__ __launch_bounds__(128)
void topk_kernel(const float* __restrict__ pd, int* __restrict__ idx) {
    int bn = blockIdx.x;                       // 0..16383 ; pd row = bn*2048
    const float* row = pd + (size_t)bn * NPTS;
    __shared__ float v[NPTS];
    __shared__ float rv[128];
    __shared__ int   ri[128];
    int t = threadIdx.x;
    for (int j = t; j < NPTS; j += 128) v[j] = row[j];
    __syncthreads();
    for (int it = 0; it < KNN; it++) {
        float bv = -INFINITY; int bi = 0x7fffffff;
        for (int j = t; j < NPTS; j += 128) {
            float x = v[j];
            if (x > bv || (x == bv && j < bi)) { bv = x; bi = j; }
        }
        rv[t] = bv; ri[t] = bi;
        __syncthreads();
        for (int s = 64; s > 0; s >>= 1) {
            if (t < s) {
                float ov = rv[t+s]; int oi = ri[t+s];
                if (ov > rv[t] || (ov == rv[t] && oi < ri[t])) { rv[t] = ov; ri[t] = oi; }
            }
            __syncthreads();
        }
        if (t == 0) { idx[bn*KNN + it] = ri[0]; v[ri[0]] = -INFINITY; }
        __syncthreads();
    }
}

// ---------------------------------------------------------------------------
// Generic NT GEMM: C[m,n] = sum_k A[row(m),k]*B[n,k]  (+ optional Tadd[m/20, n])
// A optionally gathered: row(m) = (m/(NPTS*KNN))*NPTS + gather[m]
// BM=128 BN=64 BK=16, 256 thr, 8x4 micro-tile.
// ---------------------------------------------------------------------------
__global__ __launch_bounds__(256)
void gemm_nt_kernel(const float* __restrict__ A, const float* __restrict__ B,
                    float* __restrict__ C, int M, int N, int K,
                    const int* __restrict__ gather,
                    const float* __restrict__ Tadd) {
    __shared__ float As[16][129];
    __shared__ float Bs[16][65];
    int tid = threadIdx.x;
    int tx = tid & 15;
    int ty = tid >> 4;
    int m0 = blockIdx.x * 128;
    int n0 = blockIdx.y * 64;

    float acc[8][4];
#pragma unroll
    for (int i = 0; i < 8; i++)
#pragma unroll
        for (int j = 0; j < 4; j++) acc[i][j] = 0.f;

    for (int k0 = 0; k0 < K; k0 += 16) {
#pragma unroll
        for (int i = 0; i < 8; i++) {
            int e = tid + i*256;
            int c = e & 15, r = e >> 4;
            int m = m0 + r;
            float v = 0.f;
            if (m < M && k0 + c < K) {
                int row = m;
                if (gather) {
                    int bb = m / (NPTS*KNN);
                    row = bb*NPTS + gather[m];
                }
                v = A[(size_t)row*K + k0 + c];
            }
            As[c][r] = v;
        }
#pragma unroll
        for (int i = 0; i < 4; i++) {
            int e = tid + i*256;
            int c = e & 15, r = e >> 4;
            float v = 0.f;
            if (k0 + c < K) v = B[(size_t)(n0 + r)*K + k0 + c];
            Bs[c][r] = v;
        }
        __syncthreads();
#pragma unroll
        for (int k = 0; k < 16; k++) {
            float af[8], bf[4];
#pragma unroll
            for (int i = 0; i < 8; i++) af[i] = As[k][ty*8 + i];
#pragma unroll
            for (int j = 0; j < 4; j++) bf[j] = Bs[k][tx*4 + j];
#pragma unroll
            for (int i = 0; i < 8; i++)
#pragma unroll
                for (int j = 0; j < 4; j++) acc[i][j] += af[i]*bf[j];
        }
        __syncthreads();
    }

#pragma unroll
    for (int i = 0; i < 8; i++) {
        int m = m0 + ty*8 + i;
        if (m >= M) continue;
        int pt = m / KNN;
#pragma unroll
        for (int j = 0; j < 4; j++) {
            int n = n0 + tx*4 + j;
            float v = acc[i][j];
            if (Tadd) v += Tadd[(size_t)pt*N + n];
            C[(size_t)m*N + n] = v;
        }
    }
}

// ---------------------------------------------------------------------------
// Edge reduce: per-point max/min over k, plus per-channel sum/sumsq of H
// grid: (O/64, BNTOT/64), block 256 = 64 channels x 4 point-groups x 16 points
// ---------------------------------------------------------------------------
__global__ __launch_bounds__(256)
void edge_reduce_kernel(const float* __restrict__ H, int O,
                        float* __restrict__ hmax, float* __restrict__ hmin,
                        double* __restrict__ gsum, double* __restrict__ gsum2) {
    int ol = threadIdx.x & 63;
    int gi = threadIdx.x >> 6;           // 0..3
    int o  = blockIdx.x*64 + ol;
    int p0 = blockIdx.y*64 + gi*16;
    float s = 0.f, s2 = 0.f;
    for (int pi = 0; pi < 16; pi++) {
        int p = p0 + pi;
        float mx = -INFINITY, mn = INFINITY;
        size_t base = (size_t)p*KNN*O + o;
#pragma unroll
        for (int k = 0; k < KNN; k++) {
            float v = H[base + (size_t)k*O];
            mx = fmaxf(mx, v); mn = fminf(mn, v);
            s += v; s2 += v*v;
        }
        hmax[(size_t)p*O + o] = mx;
        hmin[(size_t)p*O + o] = mn;
    }
    __shared__ float ss[4][64], ssq[4][64];
    ss[gi][ol] = s; ssq[gi][ol] = s2;
    __syncthreads();
    if (gi == 0) {
        float ts  = ss[0][ol]+ss[1][ol]+ss[2][ol]+ss[3][ol];
        float ts2 = ssq[0][ol]+ssq[1][ol]+ssq[2][ol]+ssq[3][ol];
        atomicAdd(&gsum[o],  (double)ts);
        atomicAdd(&gsum2[o], (double)ts2);
    }
}

// Column reduce for point convs (sum/sumsq per channel)
// grid: (O/64, M/256), block 256 = 64 channels x 4 groups x 64 rows
__global__ __launch_bounds__(256)
void colreduce_kernel(const float* __restrict__ P, int O,
                      double* __restrict__ gsum, double* __restrict__ gsum2) {
    int ol = threadIdx.x & 63;
    int gi = threadIdx.x >> 6;
    int o  = blockIdx.x*64 + ol;
    int r0 = blockIdx.y*256 + gi*64;
    float s = 0.f, s2 = 0.f;
    for (int r = r0; r < r0 + 64; r++) {
        float v = P[(size_t)r*O + o];
        s += v; s2 += v*v;
    }
    __shared__ float ss[4][64], ssq[4][64];
    ss[gi][ol] = s; ssq[gi][ol] = s2;
    __syncthreads();
    if (gi == 0) {
        atomicAdd(&gsum[o],  (double)(ss[0][ol]+ss[1][ol]+ss[2][ol]+ss[3][ol]));
        atomicAdd(&gsum2[o], (double)(ssq[0][ol]+ssq[1][ol]+ssq[2][ol]+ssq[3][ol]));
    }
}

__global__ void bn_params_kernel(const double* __restrict__ gsum, const double* __restrict__ gsum2,
                                 const float* __restrict__ g, const float* __restrict__ b,
                                 int O, double cnt,
                                 float* __restrict__ scale, float* __restrict__ shift) {
    int o = threadIdx.x;
    if (o >= O) return;
    double m   = gsum[o] / cnt;
    double var = gsum2[o] / cnt - m*m;
    float sc = g[o] * rsqrtf((float)var + BN_EPS);
    scale[o] = sc;
    shift[o] = b[o] - (float)m * sc;
}

__global__ void edge_finalize_kernel(const float* __restrict__ hmax, const float* __restrict__ hmin,
                                     const float* __restrict__ scale, const float* __restrict__ shift,
                                     float* __restrict__ out, int O) {
    int i = blockIdx.x*256 + threadIdx.x;
    if (i >= BNTOT*O) return;
    int o = i & (O - 1);                        // O is a power of two
    float sc = scale[o];
    float v = (sc >= 0.f ? hmax[i] : hmin[i]) * sc + shift[o];
    out[i] = v >= 0.f ? v : NEG_SLOPE*v;
}

// h6: act + global max over n per (b,o). grid (256/64, NB), block 256.
__global__ __launch_bounds__(256)
void h6_finalize_kernel(const float* __restrict__ P,
                        const float* __restrict__ scale, const float* __restrict__ shift,
                        float* __restrict__ gmax) {
    int ol = threadIdx.x & 63;
    int gi = threadIdx.x >> 6;
    int o = blockIdx.x*64 + ol;
    int b = blockIdx.y;
    float sc = scale[o], sh = shift[o];
    float mx = -INFINITY;
    for (int n = gi*512; n < (gi+1)*512; n++) {
        float v = P[((size_t)(b*NPTS + n))*256 + o]*sc + sh;
        v = v >= 0.f ? v : NEG_SLOPE*v;
        mx = fmaxf(mx, v);
    }
    __shared__ float sm[4][64];
    sm[gi][ol] = mx;
    __syncthreads();
    if (gi == 0)
        gmax[b*256 + o] = fmaxf(fmaxf(sm[0][ol], sm[1][ol]), fmaxf(sm[2][ol], sm[3][ol]));
}

__global__ void cat_kernel(const float* __restrict__ x1, const float* __restrict__ x2,
                           const float* __restrict__ x3, const float* __restrict__ x4,
                           const float* __restrict__ gmax, float* __restrict__ cat) {
    size_t i = (size_t)blockIdx.x*256 + threadIdx.x;
    if (i >= (size_t)BNTOT*768) return;
    int bn = (int)(i / 768);
    int c  = (int)(i - (size_t)bn*768);
    float v;
    if      (c < 64)  v = x1[bn*64  + c];
    else if (c < 128) v = x2[bn*64  + c - 64];
    else if (c < 256) v = x3[bn*128 + c - 128];
    else if (c < 512) v = x4[bn*256 + c - 256];
    else              v = gmax[(bn >> 11)*256 + c - 512];
    cat[i] = v;
}

// final: act + transpose (B,N,256) -> (B,256,N)
__global__ void out_transpose_kernel(const float* __restrict__ P,
                                     const float* __restrict__ scale, const float* __restrict__ shift,
                                     float* __restrict__ out) {
    __shared__ float tile[32][33];
    int b  = blockIdx.z;
    int n0 = blockIdx.x*32, o0 = blockIdx.y*32;
    int tx = threadIdx.x, ty = threadIdx.y;
    int o = o0 + tx;
    float v = P[((size_t)(b*NPTS + n0 + ty))*256 + o]*scale[o] + shift[o];
    v = v >= 0.f ? v : NEG_SLOPE*v;
    tile[ty][tx] = v;
    __syncthreads();
    out[(size_t)b*256*NPTS + (size_t)(o0 + ty)*NPTS + n0 + tx] = tile[tx][ty];
}

// ---------------------------------------------------------------------------
// Host side
// ---------------------------------------------------------------------------
static void* sym(const void* s) { void* p = nullptr; cudaGetSymbolAddress(&p, s); return p; }

extern "C" void kernel_launch(void* const* d_in, const int* in_sizes, int n_in,
                              void* d_out, int out_size) {
    const float* x  = (const float*)d_in[0];
    const float* W[4] = { (const float*)d_in[1], (const float*)d_in[4],
                          (const float*)d_in[7], (const float*)d_in[10] };
    const float* G[4] = { (const float*)d_in[2], (const float*)d_in[5],
                          (const float*)d_in[8], (const float*)d_in[11] };
    const float* Bb[4] = { (const float*)d_in[3], (const float*)d_in[6],
                           (const float*)d_in[9], (const float*)d_in[12] };
    const float* W6 = (const float*)d_in[13];
    const float* g6 = (const float*)d_in[14];
    const float* b6 = (const float*)d_in[15];
    const float* W5 = (const float*)d_in[16];
    const float* g5 = (const float*)d_in[17];
    const float* b5 = (const float*)d_in[18];

    float*  f0   = (float*)sym(g_f0);
    float*  x1   = (float*)sym(g_x1);
    float*  x2   = (float*)sym(g_x2);
    float*  x3   = (float*)sym(g_x3);
    float*  x4   = (float*)sym(g_x4);
    float*  pd   = (float*)sym(g_pd);
    int*    idx  = (int*)  sym(g_idx);
    float*  wa   = (float*)sym(g_wa);
    float*  wd   = (float*)sym(g_wd);
    float*  Tb   = (float*)sym(g_T);
    float*  Hb   = (float*)sym(g_H);
    float*  hmax = (float*)sym(g_hmax);
    float*  hmin = (float*)sym(g_hmin);
    float*  Pb   = (float*)sym(g_P);
    float*  cat  = (float*)sym(g_cat);
    float*  gmax = (float*)sym(g_gmax);
    double* s0   = (double*)sym(g_sum);
    double* s2   = (double*)sym(g_sum2);
    float*  sc   = (float*)sym(g_scale);
    float*  sh   = (float*)sym(g_shift);

    // input transpose (B,3,N) -> (B,N,3)
    transpose_in_kernel<<<(NB*3*NPTS + 255)/256, 256>>>(x, f0);

    const float* feats[4] = { f0, x1, x2, x3 };
    float*       outs [4] = { x1, x2, x3, x4 };
    const int    Cs[4] = { 3, 64, 64, 128 };
    const int    Os[4] = { 64, 64, 128, 256 };

    for (int L = 0; L < 4; L++) {
        int C = Cs[L], O = Os[L];
        const float* feat = feats[L];

        // --- kNN: direct negative squared distance + top-20 ---
        dim3 ggrid(NPTS/128, NPTS/64, NB);
        dist_kernel<<<ggrid, 256>>>(feat, pd, C);
        topk_kernel<<<BNTOT, 128>>>(pd, idx);

        // --- weights split: wa = W[:, :C], wd = W[:, C:] - W[:, :C] ---
        prep_w_kernel<<<(O*C + 255)/256, 256>>>(W[L], O, C, wa, wd);

        // --- center term T[bn,o] = feat . wd_o ---
        gemm_nt_kernel<<<dim3((BNTOT + 127)/128, O/64), 256>>>(
            feat, wd, Tb, BNTOT, O, C, nullptr, nullptr);

        // --- main gathered GEMM: H[(bn,k),o] = nbr . wa_o + T[bn,o] ---
        gemm_nt_kernel<<<dim3((MEDGE + 127)/128, O/64), 256>>>(
            feat, wa, Hb, MEDGE, O, C, idx, Tb);

        // --- BN stats + per-point max/min over k ---
        zero_stats_kernel<<<1, 256>>>(s0, s2);
        edge_reduce_kernel<<<dim3(O/64, BNTOT/64), 256>>>(Hb, O, hmax, hmin, s0, s2);
        bn_params_kernel<<<1, 256>>>(s0, s2, G[L], Bb[L], O, (double)MEDGE, sc, sh);
        edge_finalize_kernel<<<(BNTOT*O + 255)/256, 256>>>(hmax, hmin, sc, sh, outs[L], O);
    }

    // --- point conv h6 = lrelu(bn(x4 . W6^T)), then x5 = max over n ---
    gemm_nt_kernel<<<dim3(BNTOT/128, 256/64), 256>>>(x4, W6, Pb, BNTOT, 256, 256, nullptr, nullptr);
    zero_stats_kernel<<<1, 256>>>(s0, s2);
    colreduce_kernel<<<dim3(256/64, BNTOT/256), 256>>>(Pb, 256, s0, s2);
    bn_params_kernel<<<1, 256>>>(s0, s2, g6, b6, 256, (double)BNTOT, sc, sh);
    h6_finalize_kernel<<<dim3(256/64, NB), 256>>>(Pb, sc, sh, gmax);

    // --- concat [x1,x2,x3,x4,x5] -> 768 ---
    cat_kernel<<<(int)(((size_t)BNTOT*768 + 255)/256), 256>>>(x1, x2, x3, x4, gmax, cat);

    // --- final point conv + transpose output ---
    gemm_nt_kernel<<<dim3(BNTOT/128, 256/64), 256>>>(cat, W5, Pb, BNTOT, 256, 768, nullptr, nullptr);
    zero_stats_kernel<<<1, 256>>>(s0, s2);
    colreduce_kernel<<<dim3(256/64, BNTOT/256), 256>>>(Pb, 256, s0, s2);
    bn_params_kernel<<<1, 256>>>(s0, s2, g5, b5, 256, (double)BNTOT, sc, sh);
    out_transpose_kernel<<<dim3(NPTS/32, 256/32, NB), dim3(32, 32)>>>(Pb, sc, sh, (float*)d_out);
}